// round 8
// baseline (speedup 1.0000x reference)
#include <cuda_runtime.h>

// (4,4,3,192,192) fp32 -> (4,4,2,192,192): per-patch KDE entropies (R=3, h=0.1).
// R8: SMEM-staged loads (coalesced gmem -> conflict-free smem) + R7 compute:
// 4 lanes = 4 frames of one patch, fused pair loop with immediate shuffle,
// packed f32x2 (marginal, joint) accumulators.

#define WW  192
#define HW  (192 * 192)

#define CM     (-1.9537149f)      // log9 + 1.5*ln(2*pi*0.01)  (C=3 marginal)
#define CJ     (-6.1046541f)      // log9 + 3.0*ln(2*pi*0.01)  (C=6 joint)
#define LN2_9  (0.0770163534f)    // ln(2)/9
#define PSC    (8.4932200f)       // sqrt(50*log2(e)): exp(-50*d2)=ex2(-|p'|^2)

#define ONE_ONE 0x3F8000003F800000ULL

// smem tile: [3 rows][3 chan][34 xp][4 frames] floats
#define SIDX(r, c, xp, sf) ((((r) * 3 + (c)) * 34 + (xp)) * 4 + (sf))
#define TILE_N 1224   // 3*3*34*4

typedef unsigned long long u64;

static __device__ __forceinline__ float fast_ex2(float x)
{ float r; asm("ex2.approx.ftz.f32 %0, %1;" : "=f"(r) : "f"(x)); return r; }

static __device__ __forceinline__ float fast_lg2(float x)
{ float r; asm("lg2.approx.f32 %0, %1;" : "=f"(r) : "f"(x)); return r; }

static __device__ __forceinline__ u64 packf2(float lo, float hi)
{ u64 r; asm("mov.b64 %0, {%1, %2};" : "=l"(r) : "f"(lo), "f"(hi)); return r; }

static __device__ __forceinline__ void unpackf2(float& lo, float& hi, u64 v)
{ asm("mov.b64 {%0, %1}, %2;" : "=f"(lo), "=f"(hi) : "l"(v)); }

static __device__ __forceinline__ u64 addf2(u64 a, u64 b)
{ u64 r; asm("add.rn.f32x2 %0, %1, %2;" : "=l"(r) : "l"(a), "l"(b)); return r; }

static __device__ __forceinline__ u64 mulf2(u64 a, u64 b)
{ u64 r; asm("mul.rn.f32x2 %0, %1, %2;" : "=l"(r) : "l"(a), "l"(b)); return r; }

__global__ void __launch_bounds__(128)
je8_kernel(const float* __restrict__ in, float* __restrict__ out)
{
    __shared__ float sm[TILE_N];

    int tid  = threadIdx.x;
    int lane = tid & 31;
    int warp = tid >> 5;
    int sf   = lane & 3;          // frame handled by this lane
    int sub  = lane >> 2;         // patch slot within warp
    int lp   = warp * 8 + sub;    // local patch col within block, 0..31

    int x0 = blockIdx.x * 32;     // block's first patch col
    int y  = blockIdx.y;          // patch row 0..189
    int n  = blockIdx.z;

    // ---- cooperative, coalesced tile load: 4 frames x 3 chan x 3 rows x 34 px ----
    // linear idx: xp innermost (coalesced); decomposition is compile-time-cheap.
    #pragma unroll
    for (int t = tid; t < TILE_N; t += 128) {
        int xp  = t % 34;
        int rem = t / 34;         // 0..35
        int r   = rem % 3;
        int cc  = (rem / 3) % 3;
        int sfr = rem / 9;        // 0..3
        int gx  = x0 + xp; if (gx > 191) gx = 191;   // clamp (unused patches)
        float v = in[((size_t)(n * 4 + sfr) * 3 + cc) * HW + (y + r) * WW + gx] * PSC;
        sm[SIDX(r, cc, xp, sfr)] = v;
    }
    __syncthreads();

    // ---- read this lane's 3x3 patch of its frame: conflict-free LDS ----
    float px[9][3];
    #pragma unroll
    for (int c = 0; c < 3; ++c)
        #pragma unroll
        for (int dy = 0; dy < 3; ++dy)
            #pragma unroll
            for (int dx = 0; dx < 3; ++dx)
                px[dy * 3 + dx][c] = sm[SIDX(dy, c, lp + dx, sf)];

    // Shuffle source: next frame's lane (same patch); frame 3 pairs with itself.
    int src = (sf == 3) ? lane : (lane + 1);

    // ---- fused pass: 36 exps, immediate shuffle, packed (marg, joint) acc ----
    u64 sp[9];
    #pragma unroll
    for (int i = 0; i < 9; ++i) sp[i] = ONE_ONE;   // diagonal exp(0) both halves

    #pragma unroll
    for (int i = 0; i < 9; ++i) {
        #pragma unroll
        for (int j = i + 1; j < 9; ++j) {
            float d0 = px[i][0] - px[j][0];
            float d1 = px[i][1] - px[j][1];
            float d2 = px[i][2] - px[j][2];
            float nt = -(d0 * d0);
            nt = fmaf(-d1, d1, nt);
            nt = fmaf(-d2, d2, nt);
            float ee = fast_ex2(nt);
            float en = __shfl_sync(0xffffffffu, ee, src);  // lockstep: same pair
            float ej = ee * en;                            // joint exp = product
            u64 ad = packf2(ee, ej);
            sp[i] = addf2(sp[i], ad);
            sp[j] = addf2(sp[j], ad);
        }
    }

    // ---- packed product of 9 row-sums, two logs ----
    u64 pr = mulf2(mulf2(mulf2(sp[0], sp[1]), mulf2(sp[2], sp[3])),
                   mulf2(mulf2(sp[4], sp[5]), mulf2(sp[6], sp[7])));
    pr = mulf2(pr, sp[8]);
    float pm, pj;
    unpackf2(pm, pj, pr);
    float hm = CM - LN2_9 * fast_lg2(pm);
    float hj = CJ - LN2_9 * fast_lg2(pj);

    // ---- stores: this thread owns channels 2*sf, 2*sf+1 of batch n ----
    int x = x0 + lp;
    if (x < 190) {
        float* ob = out + ((size_t)(n * 4 + sf) * 2) * HW;
        int oofs = (y + 1) * WW + (x + 1);
        ob[oofs]      = hm;
        ob[HW + oofs] = hj;

        // border ring zeroing (output is poisoned 0xAA)
        if (y == 0)   { ob[x + 1] = 0.0f;            ob[HW + x + 1] = 0.0f; }
        if (y == 189) { ob[191*WW + x + 1] = 0.0f;   ob[HW + 191*WW + x + 1] = 0.0f; }
        if (x == 0) {
            ob[(y + 1) * WW] = 0.0f;      ob[HW + (y + 1) * WW] = 0.0f;
            if (y == 0)   { ob[0] = 0.0f;            ob[HW] = 0.0f; }
            if (y == 189) { ob[191*WW] = 0.0f;       ob[HW + 191*WW] = 0.0f; }
        }
        if (x == 189) {
            ob[(y + 1) * WW + 191] = 0.0f; ob[HW + (y + 1) * WW + 191] = 0.0f;
            if (y == 0)   { ob[191] = 0.0f;          ob[HW + 191] = 0.0f; }
            if (y == 189) { ob[191*WW + 191] = 0.0f; ob[HW + 191*WW + 191] = 0.0f; }
        }
    }
}

extern "C" void kernel_launch(void* const* d_in, const int* in_sizes, int n_in,
                              void* d_out, int out_size)
{
    dim3 blk(128, 1, 1);
    dim3 grd(6, 190, 4);   // 6 blocks x 32 patch cols = 192 (190 valid); 190 rows; 4 batches
    je8_kernel<<<grd, blk>>>((const float*)d_in[0], (float*)d_out);
}

// round 9
// speedup vs baseline: 1.3750x; 1.3750x over previous
#include <cuda_runtime.h>

// (4,4,3,192,192) fp32 -> (4,4,2,192,192): per-patch KDE entropies (R=3, h=0.1).
// R9: SMEM staging with free address math (warp-per-frame cooperative load,
// compile-time chan/row decomposition, conflict-free padded layout) +
// R7 compute (lane-split frames, fused shuffle, packed f32x2 accumulators).

#define WW  192
#define HW  (192 * 192)

#define CM     (-1.9537149f)      // log9 + 1.5*ln(2*pi*0.01)  (C=3 marginal)
#define CJ     (-6.1046541f)      // log9 + 3.0*ln(2*pi*0.01)  (C=6 joint)
#define LN2_9  (0.0770163534f)    // ln(2)/9
#define PSC    (8.4932200f)       // sqrt(50*log2(e)): exp(-50*d2)=ex2(-|p'|^2)

#define ONE_ONE 0x3F8000003F800000ULL

// sm[frame][chan*3+row][40]: pad 40 -> frame stride 360 = 8 (mod 32):
//   compute LDS bank = 8*sf + sub  -> all 32 lanes distinct (conflict-free)
//   store  STS bank  = lane        -> conflict-free
#define FSTRIDE 360    // 9 * 40
#define RSTRIDE 40

typedef unsigned long long u64;

static __device__ __forceinline__ float fast_ex2(float x)
{ float r; asm("ex2.approx.ftz.f32 %0, %1;" : "=f"(r) : "f"(x)); return r; }

static __device__ __forceinline__ float fast_lg2(float x)
{ float r; asm("lg2.approx.f32 %0, %1;" : "=f"(r) : "f"(x)); return r; }

static __device__ __forceinline__ u64 packf2(float lo, float hi)
{ u64 r; asm("mov.b64 %0, {%1, %2};" : "=l"(r) : "f"(lo), "f"(hi)); return r; }

static __device__ __forceinline__ void unpackf2(float& lo, float& hi, u64 v)
{ asm("mov.b64 {%0, %1}, %2;" : "=f"(lo), "=f"(hi) : "l"(v)); }

static __device__ __forceinline__ u64 addf2(u64 a, u64 b)
{ u64 r; asm("add.rn.f32x2 %0, %1, %2;" : "=l"(r) : "l"(a), "l"(b)); return r; }

static __device__ __forceinline__ u64 mulf2(u64 a, u64 b)
{ u64 r; asm("mul.rn.f32x2 %0, %1, %2;" : "=l"(r) : "l"(a), "l"(b)); return r; }

__global__ void __launch_bounds__(128)
je9_kernel(const float* __restrict__ in, float* __restrict__ out)
{
    __shared__ float sm[4 * FSTRIDE];

    int tid  = threadIdx.x;
    int lane = tid & 31;
    int warp = tid >> 5;
    int sf   = lane & 3;          // frame handled by this lane (compute phase)
    int sub  = lane >> 2;         // patch slot within warp
    int lp   = warp * 8 + sub;    // local patch col within block, 0..31

    int x0 = blockIdx.x * 32;     // block's first patch col
    int y  = blockIdx.y;          // patch row 0..189
    int n  = blockIdx.z;

    // ---- cooperative staged load: warp w loads frame w (9 rows of 34 px) ----
    // gmem base for (frame=warp): compile-time offsets per (chan, row).
    {
        const float* gb = in + ((size_t)(n * 4 + warp) * 3) * HW + y * WW + x0;
        float* sb = sm + warp * FSTRIDE;
        // main 32 columns
        #pragma unroll
        for (int it = 0; it < 9; ++it) {
            const int cc = it / 3, r = it % 3;          // compile-time
            sb[it * RSTRIDE + lane] = gb[cc * HW + r * WW + lane] * PSC;
        }
        // tail columns 32, 33 (lanes 0,1), clamp for the last block
        if (lane < 2) {
            int gx = x0 + 32 + lane;
            int cl = (gx > 191) ? (191 - x0) : (32 + lane);
            #pragma unroll
            for (int it = 0; it < 9; ++it) {
                const int cc = it / 3, r = it % 3;
                sb[it * RSTRIDE + 32 + lane] = gb[cc * HW + r * WW + cl] * PSC;
            }
        }
    }
    __syncthreads();

    // ---- read this lane's 3x3 patch of its frame: conflict-free LDS ----
    float px[9][3];
    {
        const float* sb = sm + sf * FSTRIDE + lp;
        #pragma unroll
        for (int c = 0; c < 3; ++c)
            #pragma unroll
            for (int dy = 0; dy < 3; ++dy)
                #pragma unroll
                for (int dx = 0; dx < 3; ++dx)
                    px[dy * 3 + dx][c] = sb[(c * 3 + dy) * RSTRIDE + dx];
    }

    // Shuffle source: next frame's lane (same patch); frame 3 pairs with itself.
    int src = (sf == 3) ? lane : (lane + 1);

    // ---- fused pass: 36 exps, immediate shuffle, packed (marg, joint) acc ----
    u64 sp[9];
    #pragma unroll
    for (int i = 0; i < 9; ++i) sp[i] = ONE_ONE;   // diagonal exp(0) both halves

    #pragma unroll
    for (int i = 0; i < 9; ++i) {
        #pragma unroll
        for (int j = i + 1; j < 9; ++j) {
            float d0 = px[i][0] - px[j][0];
            float d1 = px[i][1] - px[j][1];
            float d2 = px[i][2] - px[j][2];
            float nt = -(d0 * d0);
            nt = fmaf(-d1, d1, nt);
            nt = fmaf(-d2, d2, nt);
            float ee = fast_ex2(nt);
            float en = __shfl_sync(0xffffffffu, ee, src);  // lockstep: same pair
            float ej = ee * en;                            // joint exp = product
            u64 ad = packf2(ee, ej);
            sp[i] = addf2(sp[i], ad);
            sp[j] = addf2(sp[j], ad);
        }
    }

    // ---- packed product of the 9 row-sums, then two logs ----
    u64 pr = mulf2(mulf2(mulf2(sp[0], sp[1]), mulf2(sp[2], sp[3])),
                   mulf2(mulf2(sp[4], sp[5]), mulf2(sp[6], sp[7])));
    pr = mulf2(pr, sp[8]);
    float pm, pj;
    unpackf2(pm, pj, pr);
    float hm = CM - LN2_9 * fast_lg2(pm);
    float hj = CJ - LN2_9 * fast_lg2(pj);

    // ---- stores: this thread owns channels 2*sf, 2*sf+1 of batch n ----
    int x = x0 + lp;
    if (x < 190) {
        float* ob = out + ((size_t)(n * 4 + sf) * 2) * HW;
        int oofs = (y + 1) * WW + (x + 1);
        ob[oofs]      = hm;
        ob[HW + oofs] = hj;

        // border ring zeroing (output is poisoned 0xAA)
        if (y == 0)   { ob[x + 1] = 0.0f;            ob[HW + x + 1] = 0.0f; }
        if (y == 189) { ob[191*WW + x + 1] = 0.0f;   ob[HW + 191*WW + x + 1] = 0.0f; }
        if (x == 0) {
            ob[(y + 1) * WW] = 0.0f;      ob[HW + (y + 1) * WW] = 0.0f;
            if (y == 0)   { ob[0] = 0.0f;            ob[HW] = 0.0f; }
            if (y == 189) { ob[191*WW] = 0.0f;       ob[HW + 191*WW] = 0.0f; }
        }
        if (x == 189) {
            ob[(y + 1) * WW + 191] = 0.0f; ob[HW + (y + 1) * WW + 191] = 0.0f;
            if (y == 0)   { ob[191] = 0.0f;          ob[HW + 191] = 0.0f; }
            if (y == 189) { ob[191*WW + 191] = 0.0f; ob[HW + 191*WW + 191] = 0.0f; }
        }
    }
}

extern "C" void kernel_launch(void* const* d_in, const int* in_sizes, int n_in,
                              void* d_out, int out_size)
{
    dim3 blk(128, 1, 1);
    dim3 grd(6, 190, 4);   // 6 blocks x 32 patch cols = 192 (190 valid); 190 rows; 4 batches
    je9_kernel<<<grd, blk>>>((const float*)d_in[0], (float*)d_out);
}